// round 1
// baseline (speedup 1.0000x reference)
#include <cuda_runtime.h>
#include <math.h>

// Problem constants (fixed by the dataset)
#define NTOK 8192
#define DDIM 2048
#define SCALING_F (16.0f / 2048.0f)
#define EPS_F 1e-12f

// Scratch: static device globals (allocation-free per harness rules).
__device__ float g_T1[(size_t)NTOK * DDIM];   // 64 MB
__device__ float g_T2[(size_t)NTOK * DDIM];   // 64 MB
__device__ float g_colscale[DDIM];
__device__ float g_mag;

// ---------------------------------------------------------------------------
// Prep kernel 1: g_mag = ||magnitude||_2
// ---------------------------------------------------------------------------
__global__ void mag_kernel(const float* __restrict__ magnitude) {
    __shared__ float red[256];
    float s = 0.0f;
    for (int i = threadIdx.x; i < DDIM; i += 256) {
        float v = magnitude[i];
        s += v * v;
    }
    red[threadIdx.x] = s;
    __syncthreads();
    for (int off = 128; off > 0; off >>= 1) {
        if (threadIdx.x < off) red[threadIdx.x] += red[threadIdx.x + off];
        __syncthreads();
    }
    if (threadIdx.x == 0) g_mag = sqrtf(red[0]);
}

// ---------------------------------------------------------------------------
// Prep kernel 2: g_colscale[o] = g_mag / max(||direction[o,:]||, eps)
// ---------------------------------------------------------------------------
__global__ void colscale_kernel(const float* __restrict__ direction) {
    int o = blockIdx.x;
    const float* row = direction + (size_t)o * DDIM;
    float s = 0.0f;
    for (int i = threadIdx.x; i < DDIM; i += 256) {
        float v = row[i];
        s += v * v;
    }
    __shared__ float red[256];
    red[threadIdx.x] = s;
    __syncthreads();
    for (int off = 128; off > 0; off >>= 1) {
        if (threadIdx.x < off) red[threadIdx.x] += red[threadIdx.x + off];
        __syncthreads();
    }
    if (threadIdx.x == 0) {
        float dn = sqrtf(red[0]);
        g_colscale[o] = g_mag / fmaxf(dn, EPS_F);
    }
}

// ---------------------------------------------------------------------------
// SGEMM: C[M=8192, N=2048] = alpha * A[8192, 2048] * op(B), fp32.
//   BT=false: op(B)[k][n] = B[k*DDIM + n]      (B row-major [K, N])
//   BT=true : op(B)[k][n] = B[n*DDIM + k]      (B row-major [N, K], transposed)
//   USE_CS : multiply column n of C by colScale[n] in the epilogue.
// Tile: 128x128x8, 256 threads, 8x8 per thread, register-prefetch double buffer.
// ---------------------------------------------------------------------------
template <bool BT, bool USE_CS>
__global__ __launch_bounds__(256, 2)
void sgemm_kernel(const float* __restrict__ A, const float* __restrict__ B,
                  float* __restrict__ C, float alpha,
                  const float* __restrict__ colScale)
{
    constexpr int BM = 128, BN = 128, BK = 8;

    __shared__ float As[BK][BM];   // transposed: As[k][m]
    __shared__ float Bs[BK][BN];   // Bs[k][n]

    const int tid = threadIdx.x;
    const int m0 = blockIdx.y * BM;
    const int n0 = blockIdx.x * BN;

    // 16x16 thread grid over the 128x128 C tile, 8x8 fragment each
    const int trow = (tid >> 4) * 8;   // 0..120
    const int tcol = (tid & 15) * 8;   // 0..120

    // A-load mapping: 128 rows x 8 cols, one float4 per thread
    const int a_row = tid >> 1;        // 0..127
    const int a_col = (tid & 1) * 4;   // 0 or 4
    // B (non-trans) mapping: 8 rows x 128 cols, one float4 per thread
    const int b_row = tid >> 5;        // 0..7
    const int b_col = (tid & 31) * 4;  // 0..124

    const float* Aptr = A + (size_t)(m0 + a_row) * DDIM + a_col;
    const float* Bptr;
    if (BT) Bptr = B + (size_t)(n0 + a_row) * DDIM + a_col;      // direction[n, k]
    else    Bptr = B + (size_t)b_row * DDIM + (n0 + b_col);      // B[k, n]

    float acc[8][8];
    #pragma unroll
    for (int i = 0; i < 8; i++)
        #pragma unroll
        for (int j = 0; j < 8; j++) acc[i][j] = 0.0f;

    // Prologue: fetch k-tile 0 into registers
    float4 aReg = *(const float4*)(Aptr);
    float4 bReg = BT ? *(const float4*)(Bptr)
                     : *(const float4*)(Bptr);

    for (int k0 = 0; k0 < DDIM; k0 += BK) {
        // Commit current tile to smem
        As[a_col + 0][a_row] = aReg.x;
        As[a_col + 1][a_row] = aReg.y;
        As[a_col + 2][a_row] = aReg.z;
        As[a_col + 3][a_row] = aReg.w;
        if (BT) {
            Bs[a_col + 0][a_row] = bReg.x;
            Bs[a_col + 1][a_row] = bReg.y;
            Bs[a_col + 2][a_row] = bReg.z;
            Bs[a_col + 3][a_row] = bReg.w;
        } else {
            *(float4*)&Bs[b_row][b_col] = bReg;
        }
        __syncthreads();

        // Prefetch next tile into registers (overlaps with compute below)
        if (k0 + BK < DDIM) {
            aReg = *(const float4*)(Aptr + (k0 + BK));
            if (BT) bReg = *(const float4*)(Bptr + (k0 + BK));
            else    bReg = *(const float4*)(Bptr + (size_t)(k0 + BK) * DDIM);
        }

        // Compute on current smem tile
        #pragma unroll
        for (int kk = 0; kk < BK; ++kk) {
            float4 a0 = *(const float4*)&As[kk][trow];
            float4 a1 = *(const float4*)&As[kk][trow + 4];
            float4 b0 = *(const float4*)&Bs[kk][tcol];
            float4 b1 = *(const float4*)&Bs[kk][tcol + 4];
            float ar[8] = {a0.x, a0.y, a0.z, a0.w, a1.x, a1.y, a1.z, a1.w};
            float br[8] = {b0.x, b0.y, b0.z, b0.w, b1.x, b1.y, b1.z, b1.w};
            #pragma unroll
            for (int i = 0; i < 8; i++)
                #pragma unroll
                for (int j = 0; j < 8; j++)
                    acc[i][j] = fmaf(ar[i], br[j], acc[i][j]);
        }
        __syncthreads();
    }

    // Epilogue: scale + (optional) per-column colScale, vectorized stores
    float cs[8];
    #pragma unroll
    for (int j = 0; j < 8; j++)
        cs[j] = USE_CS ? (alpha * colScale[n0 + tcol + j]) : alpha;

    #pragma unroll
    for (int i = 0; i < 8; i++) {
        float* crow = C + (size_t)(m0 + trow + i) * DDIM + (n0 + tcol);
        float4 v0, v1;
        v0.x = acc[i][0] * cs[0];  v0.y = acc[i][1] * cs[1];
        v0.z = acc[i][2] * cs[2];  v0.w = acc[i][3] * cs[3];
        v1.x = acc[i][4] * cs[4];  v1.y = acc[i][5] * cs[5];
        v1.z = acc[i][6] * cs[6];  v1.w = acc[i][7] * cs[7];
        *(float4*)(crow + 0) = v0;
        *(float4*)(crow + 4) = v1;
    }
}

// ---------------------------------------------------------------------------
// Launch: mag -> colscale -> GEMM1 -> GEMM2 -> GEMM3 (stream-ordered)
// ---------------------------------------------------------------------------
extern "C" void kernel_launch(void* const* d_in, const int* in_sizes, int n_in,
                              void* d_out, int out_size) {
    const float* x         = (const float*)d_in[0];  // [N, D]
    const float* lora_A    = (const float*)d_in[1];  // [D, D]  [r, i]
    const float* lora_B    = (const float*)d_in[2];  // [D, D]  [o, r]
    const float* magnitude = (const float*)d_in[3];  // [D]
    const float* direction = (const float*)d_in[4];  // [D, D]  [o, r]
    float* out = (float*)d_out;                      // [N, D]

    float* t1 = nullptr;
    float* t2 = nullptr;
    float* colscale = nullptr;
    cudaGetSymbolAddress((void**)&t1, g_T1);
    cudaGetSymbolAddress((void**)&t2, g_T2);
    cudaGetSymbolAddress((void**)&colscale, g_colscale);

    // Tiny prep kernels
    mag_kernel<<<1, 256>>>(magnitude);
    colscale_kernel<<<DDIM, 256>>>(direction);

    dim3 grid(DDIM / 128, NTOK / 128);  // (16, 64)
    dim3 block(256);

    // GEMM1: T1[n,r] = sum_o x[n,o] * lora_B[o,r]
    sgemm_kernel<false, false><<<grid, block>>>(x, lora_B, t1, 1.0f, nullptr);
    // GEMM2: T2[n,i] = SCALING * sum_r T1[n,r] * lora_A[r,i]
    sgemm_kernel<false, false><<<grid, block>>>(t1, lora_A, t2, SCALING_F, nullptr);
    // GEMM3: out[n,o] = colscale[o] * sum_r T2[n,r] * direction[o,r]
    sgemm_kernel<true, true><<<grid, block>>>(t2, direction, out, 1.0f, colscale);
}

// round 3
// speedup vs baseline: 5.6215x; 5.6215x over previous
#include <cuda_runtime.h>
#include <cuda_bf16.h>
#include <cstdint>
#include <math.h>

typedef __nv_bfloat16 bf16;

#define NTOK 8192
#define DDIM 2048
#define KDIM 2048
#define SCALING_F (16.0f / 2048.0f)
#define EPS_F 1e-12f

// ---------------------------------------------------------------------------
// Static device scratch (allocation-free per harness rules)
// ---------------------------------------------------------------------------
__device__ bf16 g_x_hi [(size_t)NTOK * DDIM];
__device__ bf16 g_x_lo [(size_t)NTOK * DDIM];
__device__ bf16 g_lB_hi[(size_t)DDIM * DDIM];
__device__ bf16 g_lB_lo[(size_t)DDIM * DDIM];
__device__ bf16 g_lAT_hi[(size_t)DDIM * DDIM];   // lora_A transposed [i, r]
__device__ bf16 g_lAT_lo[(size_t)DDIM * DDIM];
__device__ bf16 g_dir_hi[(size_t)DDIM * DDIM];
__device__ bf16 g_dir_lo[(size_t)DDIM * DDIM];
__device__ bf16 g_P_hi [(size_t)DDIM * DDIM];    // P = lora_B @ lora_A  [o, i]
__device__ bf16 g_P_lo [(size_t)DDIM * DDIM];
__device__ bf16 g_QT_hi[(size_t)DDIM * DDIM];    // QT[oo,o] = cs[oo]*(dir @ P^T)
__device__ bf16 g_QT_lo[(size_t)DDIM * DDIM];
__device__ float g_cs[DDIM];
__device__ float g_mag;

// ---------------------------------------------------------------------------
// PTX helpers — standard features only (sm_80+): cp.async, ldmatrix, mma.sync
// ---------------------------------------------------------------------------
__device__ __forceinline__ uint32_t smem_u32(const void* p) {
    uint32_t a;
    asm("{ .reg .u64 t; cvta.to.shared.u64 t, %1; cvt.u32.u64 %0, t; }" : "=r"(a) : "l"(p));
    return a;
}

__device__ __forceinline__ void cp_async16(uint32_t dst, const void* src) {
    asm volatile("cp.async.cg.shared.global [%0], [%1], 16;" :: "r"(dst), "l"(src));
}
__device__ __forceinline__ void cp_commit() { asm volatile("cp.async.commit_group;" ::: "memory"); }
template <int N>
__device__ __forceinline__ void cp_wait() { asm volatile("cp.async.wait_group %0;" :: "n"(N) : "memory"); }

#define LDSM_X4(r0, r1, r2, r3, addr) \
    asm volatile("ldmatrix.sync.aligned.m8n8.x4.shared.b16 {%0,%1,%2,%3}, [%4];" \
        : "=r"(r0), "=r"(r1), "=r"(r2), "=r"(r3) : "r"(addr))

__device__ __forceinline__ void mma_bf16(float* c, const uint32_t* a, const uint32_t* b) {
    asm volatile(
        "mma.sync.aligned.m16n8k16.row.col.f32.bf16.bf16.f32 "
        "{%0,%1,%2,%3}, {%4,%5,%6,%7}, {%8,%9}, {%0,%1,%2,%3};"
        : "+f"(c[0]), "+f"(c[1]), "+f"(c[2]), "+f"(c[3])
        : "r"(a[0]), "r"(a[1]), "r"(a[2]), "r"(a[3]), "r"(b[0]), "r"(b[1]));
}

// ---------------------------------------------------------------------------
// Prep kernels
// ---------------------------------------------------------------------------
__global__ void mag_kernel(const float* __restrict__ magnitude) {
    __shared__ float red[256];
    float s = 0.0f;
    for (int i = threadIdx.x; i < DDIM; i += 256) { float v = magnitude[i]; s += v * v; }
    red[threadIdx.x] = s; __syncthreads();
    for (int off = 128; off > 0; off >>= 1) {
        if (threadIdx.x < off) red[threadIdx.x] += red[threadIdx.x + off];
        __syncthreads();
    }
    if (threadIdx.x == 0) g_mag = sqrtf(red[0]);
}

__global__ void colscale_kernel(const float* __restrict__ direction) {
    int o = blockIdx.x;
    const float* row = direction + (size_t)o * DDIM;
    float s = 0.0f;
    for (int i = threadIdx.x; i < DDIM; i += 256) { float v = row[i]; s += v * v; }
    __shared__ float red[256];
    red[threadIdx.x] = s; __syncthreads();
    for (int off = 128; off > 0; off >>= 1) {
        if (threadIdx.x < off) red[threadIdx.x] += red[threadIdx.x + off];
        __syncthreads();
    }
    if (threadIdx.x == 0)
        g_cs[o] = g_mag * SCALING_F / fmaxf(sqrtf(red[0]), EPS_F);
}

// fp32 -> (bf16 hi, bf16 lo) split, vectorized
__global__ void split_convert(const float* __restrict__ in, bf16* __restrict__ hi,
                              bf16* __restrict__ lo, int n4) {
    int i = blockIdx.x * blockDim.x + threadIdx.x;
    if (i >= n4) return;
    float4 v = ((const float4*)in)[i];
    bf16 h0 = __float2bfloat16(v.x), h1 = __float2bfloat16(v.y);
    bf16 h2 = __float2bfloat16(v.z), h3 = __float2bfloat16(v.w);
    bf16 l0 = __float2bfloat16(v.x - __bfloat162float(h0));
    bf16 l1 = __float2bfloat16(v.y - __bfloat162float(h1));
    bf16 l2 = __float2bfloat16(v.z - __bfloat162float(h2));
    bf16 l3 = __float2bfloat16(v.w - __bfloat162float(h3));
    __nv_bfloat162 a, b;
    a.x = h0; a.y = h1; b.x = h2; b.y = h3;
    ((__nv_bfloat162*)hi)[i * 2] = a;     ((__nv_bfloat162*)hi)[i * 2 + 1] = b;
    a.x = l0; a.y = l1; b.x = l2; b.y = l3;
    ((__nv_bfloat162*)lo)[i * 2] = a;     ((__nv_bfloat162*)lo)[i * 2 + 1] = b;
}

// fp32 [R, C] -> transposed split bf16 [C, R]   (R = C = DDIM)
__global__ void transpose_split(const float* __restrict__ in, bf16* __restrict__ hi,
                                bf16* __restrict__ lo) {
    __shared__ float t[32][33];
    int bx = blockIdx.x * 32, by = blockIdx.y * 32;
    int tx = threadIdx.x, ty = threadIdx.y;  // 32 x 8
    #pragma unroll
    for (int j = 0; j < 32; j += 8)
        t[ty + j][tx] = in[(size_t)(by + ty + j) * DDIM + bx + tx];
    __syncthreads();
    #pragma unroll
    for (int j = 0; j < 32; j += 8) {
        float v = t[tx][ty + j];
        size_t o = (size_t)(bx + ty + j) * DDIM + by + tx;
        bf16 h = __float2bfloat16(v);
        hi[o] = h;
        lo[o] = __float2bfloat16(v - __bfloat162float(h));
    }
}

// ---------------------------------------------------------------------------
// Split-bf16 GEMM via mma.sync:  C[M,N] = A[M,K] * B[N,K]^T,  K = 2048.
//   A,B as (hi, lo) bf16 pairs; acc = Ah*Bh + Ah*Bl + Al*Bh in fp32 registers.
//   EPI 0: fp32 out.  EPI 1: split bf16 out.  EPI 2: split out scaled by rowscale[m].
// CTA tile 128x128x64, 8 warps (warp tile 64x32), 3-stage cp.async pipeline,
// SW128-style XOR swizzle, ldmatrix fragments.
// ---------------------------------------------------------------------------
template <int EPI>
__global__ __launch_bounds__(256, 1)
void gemm_split(const bf16* __restrict__ Ah_g, const bf16* __restrict__ Al_g,
                const bf16* __restrict__ Bh_g, const bf16* __restrict__ Bl_g,
                float* __restrict__ Cf, bf16* __restrict__ Chi, bf16* __restrict__ Clo,
                const float* __restrict__ rowscale)
{
    extern __shared__ __align__(128) char smem[];
    const uint32_t sb = smem_u32(smem);

    constexpr int K = KDIM, BK = 64, NC = K / BK, S = 3;
    constexpr uint32_t TILE = 128 * 128;     // one operand tile: 128 rows x 128 bytes
    constexpr uint32_t STAGE = 4 * TILE;     // Ah, Al, Bh, Bl = 64 KB

    const int tid = threadIdx.x;
    const int m0 = blockIdx.y * 128;
    const int n0 = blockIdx.x * 128;
    const int ldc = gridDim.x * 128;
    const int wid = tid >> 5, lane = tid & 31;
    const int wm = (wid >> 2) * 64;   // warp row offset (0 / 64)
    const int wn = (wid & 3) * 32;    // warp col offset (0/32/64/96)

    // cp.async mapping: each thread does 16 x 16B per stage
    const int lrow = tid >> 3;        // 0..31
    const int lg   = tid & 7;         // 16B group within 128B row
    const bf16* gp0 = Ah_g + (size_t)m0 * K;
    const bf16* gp1 = Al_g + (size_t)m0 * K;
    const bf16* gp2 = Bh_g + (size_t)n0 * K;
    const bf16* gp3 = Bl_g + (size_t)n0 * K;

    auto load_stage = [&](int slot, int c) {
        const uint32_t base = sb + (uint32_t)slot * STAGE;
        const int k0 = c * BK + lg * 8;
        #pragma unroll
        for (int t = 0; t < 4; t++) {
            const bf16* bp = (t == 0) ? gp0 : (t == 1) ? gp1 : (t == 2) ? gp2 : gp3;
            #pragma unroll
            for (int j = 0; j < 4; j++) {
                const int row = lrow + 32 * j;
                uint32_t dst = base + (uint32_t)t * TILE + (uint32_t)row * 128
                             + (((uint32_t)lg * 16) ^ (((uint32_t)row & 7) << 4));
                cp_async16(dst, bp + (size_t)row * K + k0);
            }
        }
        cp_commit();
    };

    float acc[4][4][4];
    #pragma unroll
    for (int a = 0; a < 4; a++)
        #pragma unroll
        for (int b = 0; b < 4; b++)
            #pragma unroll
            for (int q = 0; q < 4; q++) acc[a][b][q] = 0.0f;

    load_stage(0, 0);
    load_stage(1, 1);

    // ldmatrix lane components
    const int a_row_l = lane & 15;                       // row within 16-row tile
    const int a_kb_l  = (lane >> 4) * 16;                // 0 or 16 bytes (k halves)
    const int b_n_l   = (lane & 7) + ((lane >> 4) << 3); // row within 16-col group
    const int b_kb_l  = ((lane >> 3) & 1) * 16;

    for (int c = 0; c < NC; c++) {
        if (c + 1 < NC) cp_wait<1>(); else cp_wait<0>();
        __syncthreads();
        if (c + 2 < NC) load_stage((c + 2) % S, c + 2);

        const uint32_t stg = sb + (uint32_t)(c % S) * STAGE;
        const uint32_t As_h = stg, As_l = stg + TILE;
        const uint32_t Bs_h = stg + 2 * TILE, Bs_l = stg + 3 * TILE;

        #pragma unroll
        for (int s = 0; s < 4; s++) {          // 4 k16 steps per 64-chunk
            const int kb = s * 32;             // byte offset of this k16
            uint32_t ah[4][4], al[4][4], bh[4][2], bl[4][2];
            #pragma unroll
            for (int mi = 0; mi < 4; mi++) {
                const int row = wm + mi * 16 + a_row_l;
                const uint32_t off = (uint32_t)row * 128
                    + (((uint32_t)(kb + a_kb_l)) ^ (((uint32_t)row & 7) << 4));
                LDSM_X4(ah[mi][0], ah[mi][1], ah[mi][2], ah[mi][3], As_h + off);
                LDSM_X4(al[mi][0], al[mi][1], al[mi][2], al[mi][3], As_l + off);
            }
            #pragma unroll
            for (int nj2 = 0; nj2 < 2; nj2++) {
                const int nr = wn + nj2 * 16 + b_n_l;
                const uint32_t off = (uint32_t)nr * 128
                    + (((uint32_t)(kb + b_kb_l)) ^ (((uint32_t)nr & 7) << 4));
                LDSM_X4(bh[2*nj2][0], bh[2*nj2][1], bh[2*nj2+1][0], bh[2*nj2+1][1], Bs_h + off);
                LDSM_X4(bl[2*nj2][0], bl[2*nj2][1], bl[2*nj2+1][0], bl[2*nj2+1][1], Bs_l + off);
            }
            #pragma unroll
            for (int mi = 0; mi < 4; mi++)
                #pragma unroll
                for (int nj = 0; nj < 4; nj++) {
                    mma_bf16(acc[mi][nj], ah[mi], bh[nj]);
                    mma_bf16(acc[mi][nj], ah[mi], bl[nj]);
                    mma_bf16(acc[mi][nj], al[mi], bh[nj]);
                }
        }
    }

    // ---------------- epilogue ----------------
    const int g  = lane >> 2;
    const int t4 = lane & 3;
    #pragma unroll
    for (int mi = 0; mi < 4; mi++) {
        const int r0 = m0 + wm + mi * 16 + g;
        const int r1 = r0 + 8;
        float rs0 = 1.0f, rs1 = 1.0f;
        if (EPI == 2) { rs0 = rowscale[r0]; rs1 = rowscale[r1]; }
        #pragma unroll
        for (int nj = 0; nj < 4; nj++) {
            const int col = n0 + wn + nj * 8 + t4 * 2;
            float c0 = acc[mi][nj][0], c1 = acc[mi][nj][1];
            float c2 = acc[mi][nj][2], c3 = acc[mi][nj][3];
            if (EPI == 0) {
                float2 v0; v0.x = c0; v0.y = c1;
                float2 v1; v1.x = c2; v1.y = c3;
                *(float2*)(Cf + (size_t)r0 * ldc + col) = v0;
                *(float2*)(Cf + (size_t)r1 * ldc + col) = v1;
            } else {
                c0 *= rs0; c1 *= rs0; c2 *= rs1; c3 *= rs1;
                bf16 h0 = __float2bfloat16(c0), h1 = __float2bfloat16(c1);
                bf16 h2 = __float2bfloat16(c2), h3 = __float2bfloat16(c3);
                __nv_bfloat162 hp0; hp0.x = h0; hp0.y = h1;
                __nv_bfloat162 hp1; hp1.x = h2; hp1.y = h3;
                __nv_bfloat162 lp0, lp1;
                lp0.x = __float2bfloat16(c0 - __bfloat162float(h0));
                lp0.y = __float2bfloat16(c1 - __bfloat162float(h1));
                lp1.x = __float2bfloat16(c2 - __bfloat162float(h2));
                lp1.y = __float2bfloat16(c3 - __bfloat162float(h3));
                *(__nv_bfloat162*)(Chi + (size_t)r0 * ldc + col) = hp0;
                *(__nv_bfloat162*)(Chi + (size_t)r1 * ldc + col) = hp1;
                *(__nv_bfloat162*)(Clo + (size_t)r0 * ldc + col) = lp0;
                *(__nv_bfloat162*)(Clo + (size_t)r1 * ldc + col) = lp1;
            }
        }
    }
}

// ---------------------------------------------------------------------------
// Launch
// ---------------------------------------------------------------------------
static constexpr int GEMM_SMEM = 3 * 4 * 128 * 128;  // 196608 bytes

extern "C" void kernel_launch(void* const* d_in, const int* in_sizes, int n_in,
                              void* d_out, int out_size) {
    const float* x         = (const float*)d_in[0];  // [N, D]
    const float* lora_A    = (const float*)d_in[1];  // [r, i]
    const float* lora_B    = (const float*)d_in[2];  // [o, r]
    const float* magnitude = (const float*)d_in[3];  // [D]
    const float* direction = (const float*)d_in[4];  // [oo, i]
    float* out = (float*)d_out;                      // [N, D]

    bf16 *x_hi, *x_lo, *lB_hi, *lB_lo, *lAT_hi, *lAT_lo, *dir_hi, *dir_lo;
    bf16 *P_hi, *P_lo, *QT_hi, *QT_lo;
    float* cs;
    cudaGetSymbolAddress((void**)&x_hi, g_x_hi);   cudaGetSymbolAddress((void**)&x_lo, g_x_lo);
    cudaGetSymbolAddress((void**)&lB_hi, g_lB_hi); cudaGetSymbolAddress((void**)&lB_lo, g_lB_lo);
    cudaGetSymbolAddress((void**)&lAT_hi, g_lAT_hi); cudaGetSymbolAddress((void**)&lAT_lo, g_lAT_lo);
    cudaGetSymbolAddress((void**)&dir_hi, g_dir_hi); cudaGetSymbolAddress((void**)&dir_lo, g_dir_lo);
    cudaGetSymbolAddress((void**)&P_hi, g_P_hi);   cudaGetSymbolAddress((void**)&P_lo, g_P_lo);
    cudaGetSymbolAddress((void**)&QT_hi, g_QT_hi); cudaGetSymbolAddress((void**)&QT_lo, g_QT_lo);
    cudaGetSymbolAddress((void**)&cs, g_cs);

    cudaFuncSetAttribute(gemm_split<0>, cudaFuncAttributeMaxDynamicSharedMemorySize, GEMM_SMEM);
    cudaFuncSetAttribute(gemm_split<1>, cudaFuncAttributeMaxDynamicSharedMemorySize, GEMM_SMEM);
    cudaFuncSetAttribute(gemm_split<2>, cudaFuncAttributeMaxDynamicSharedMemorySize, GEMM_SMEM);

    // Prep: norms + split conversions
    mag_kernel<<<1, 256>>>(magnitude);
    colscale_kernel<<<DDIM, 256>>>(direction);

    const int nX4 = (NTOK * DDIM) / 4, nD4 = (DDIM * DDIM) / 4;
    split_convert<<<(nX4 + 255) / 256, 256>>>(x, x_hi, x_lo, nX4);
    split_convert<<<(nD4 + 255) / 256, 256>>>(lora_B, lB_hi, lB_lo, nD4);
    split_convert<<<(nD4 + 255) / 256, 256>>>(direction, dir_hi, dir_lo, nD4);
    dim3 tgrid(DDIM / 32, DDIM / 32), tblk(32, 8);
    transpose_split<<<tgrid, tblk>>>(lora_A, lAT_hi, lAT_lo);

    // GEMM 1: P[o,i] = sum_r lora_B[o,r] * lora_A_T[i,r]   (split epilogue)
    dim3 gs(DDIM / 128, DDIM / 128);
    gemm_split<1><<<gs, 256, GEMM_SMEM>>>(lB_hi, lB_lo, lAT_hi, lAT_lo,
                                          nullptr, P_hi, P_lo, nullptr);
    // GEMM 2: QT[oo,o] = cs[oo] * sum_i direction[oo,i] * P[o,i]  (split + rowscale)
    gemm_split<2><<<gs, 256, GEMM_SMEM>>>(dir_hi, dir_lo, P_hi, P_lo,
                                          nullptr, QT_hi, QT_lo, cs);
    // GEMM 3: out[n,oo] = sum_o x[n,o] * QT[oo,o]   (fp32 epilogue)
    dim3 gb(DDIM / 128, NTOK / 128);
    gemm_split<0><<<gb, 256, GEMM_SMEM>>>(x_hi, x_lo, QT_hi, QT_lo,
                                          out, nullptr, nullptr, nullptr);
}

// round 4
// speedup vs baseline: 5.6401x; 1.0033x over previous
#include <cuda_runtime.h>
#include <cuda_bf16.h>
#include <cstdint>
#include <math.h>

typedef __nv_bfloat16 bf16;

#define NTOK 8192
#define DDIM 2048
#define KDIM 2048
#define SCALING_F (16.0f / 2048.0f)
#define EPS_F 1e-12f

// ---------------------------------------------------------------------------
// Static device scratch (allocation-free per harness rules)
// ---------------------------------------------------------------------------
__device__ bf16 g_x_hi [(size_t)NTOK * DDIM];
__device__ bf16 g_x_lo [(size_t)NTOK * DDIM];
__device__ bf16 g_lB_hi[(size_t)DDIM * DDIM];
__device__ bf16 g_lB_lo[(size_t)DDIM * DDIM];
__device__ bf16 g_lAT_hi[(size_t)DDIM * DDIM];   // lora_A transposed [i, r]
__device__ bf16 g_lAT_lo[(size_t)DDIM * DDIM];
__device__ bf16 g_dir_hi[(size_t)DDIM * DDIM];
__device__ bf16 g_dir_lo[(size_t)DDIM * DDIM];
__device__ bf16 g_P_hi [(size_t)DDIM * DDIM];    // P = lora_B @ lora_A  [o, i]
__device__ bf16 g_P_lo [(size_t)DDIM * DDIM];
__device__ bf16 g_QT_hi[(size_t)DDIM * DDIM];    // QT[oo,o] = cs[oo]*(dir @ P^T)
__device__ bf16 g_QT_lo[(size_t)DDIM * DDIM];
__device__ float g_cs[DDIM];
__device__ float g_mag;

// ---------------------------------------------------------------------------
// PTX helpers — standard features only (sm_80+): cp.async, ldmatrix, mma.sync
// ---------------------------------------------------------------------------
__device__ __forceinline__ uint32_t smem_u32(const void* p) {
    uint32_t a;
    asm("{ .reg .u64 t; cvta.to.shared.u64 t, %1; cvt.u32.u64 %0, t; }" : "=r"(a) : "l"(p));
    return a;
}

__device__ __forceinline__ void cp_async16(uint32_t dst, const void* src) {
    asm volatile("cp.async.cg.shared.global [%0], [%1], 16;" :: "r"(dst), "l"(src));
}
__device__ __forceinline__ void cp_commit() { asm volatile("cp.async.commit_group;" ::: "memory"); }
template <int N>
__device__ __forceinline__ void cp_wait() { asm volatile("cp.async.wait_group %0;" :: "n"(N) : "memory"); }

#define LDSM_X4(r0, r1, r2, r3, addr) \
    asm volatile("ldmatrix.sync.aligned.m8n8.x4.shared.b16 {%0,%1,%2,%3}, [%4];" \
        : "=r"(r0), "=r"(r1), "=r"(r2), "=r"(r3) : "r"(addr))

__device__ __forceinline__ void mma_bf16(float* c, const uint32_t* a, const uint32_t* b) {
    asm volatile(
        "mma.sync.aligned.m16n8k16.row.col.f32.bf16.bf16.f32 "
        "{%0,%1,%2,%3}, {%4,%5,%6,%7}, {%8,%9}, {%0,%1,%2,%3};"
        : "+f"(c[0]), "+f"(c[1]), "+f"(c[2]), "+f"(c[3])
        : "r"(a[0]), "r"(a[1]), "r"(a[2]), "r"(a[3]), "r"(b[0]), "r"(b[1]));
}

// ---------------------------------------------------------------------------
// Prep kernels
// ---------------------------------------------------------------------------
__global__ void mag_kernel(const float* __restrict__ magnitude) {
    __shared__ float red[256];
    float s = 0.0f;
    for (int i = threadIdx.x; i < DDIM; i += 256) { float v = magnitude[i]; s += v * v; }
    red[threadIdx.x] = s; __syncthreads();
    for (int off = 128; off > 0; off >>= 1) {
        if (threadIdx.x < off) red[threadIdx.x] += red[threadIdx.x + off];
        __syncthreads();
    }
    if (threadIdx.x == 0) g_mag = sqrtf(red[0]);
}

__global__ void colscale_kernel(const float* __restrict__ direction) {
    int o = blockIdx.x;
    const float* row = direction + (size_t)o * DDIM;
    float s = 0.0f;
    for (int i = threadIdx.x; i < DDIM; i += 256) { float v = row[i]; s += v * v; }
    __shared__ float red[256];
    red[threadIdx.x] = s; __syncthreads();
    for (int off = 128; off > 0; off >>= 1) {
        if (threadIdx.x < off) red[threadIdx.x] += red[threadIdx.x + off];
        __syncthreads();
    }
    if (threadIdx.x == 0)
        g_cs[o] = g_mag * SCALING_F / fmaxf(sqrtf(red[0]), EPS_F);
}

// fp32 -> (bf16 hi, bf16 lo) split; 8 floats/thread, 16B stores
__global__ void split_convert(const float* __restrict__ in, bf16* __restrict__ hi,
                              bf16* __restrict__ lo, int n8) {
    int i = blockIdx.x * blockDim.x + threadIdx.x;
    if (i >= n8) return;
    float4 a = ((const float4*)in)[i * 2];
    float4 b = ((const float4*)in)[i * 2 + 1];
    float v[8] = {a.x, a.y, a.z, a.w, b.x, b.y, b.z, b.w};
    uint32_t hw[4], lw[4];
    #pragma unroll
    for (int q = 0; q < 4; q++) {
        bf16 h0 = __float2bfloat16(v[q * 2]);
        bf16 h1 = __float2bfloat16(v[q * 2 + 1]);
        __nv_bfloat162 hp; hp.x = h0; hp.y = h1;
        hw[q] = *(uint32_t*)&hp;
        __nv_bfloat162 lp;
        lp.x = __float2bfloat16(v[q * 2] - __bfloat162float(h0));
        lp.y = __float2bfloat16(v[q * 2 + 1] - __bfloat162float(h1));
        lw[q] = *(uint32_t*)&lp;
    }
    uint4 hv; hv.x = hw[0]; hv.y = hw[1]; hv.z = hw[2]; hv.w = hw[3];
    uint4 lv; lv.x = lw[0]; lv.y = lw[1]; lv.z = lw[2]; lv.w = lw[3];
    ((uint4*)hi)[i] = hv;
    ((uint4*)lo)[i] = lv;
}

// fp32 [R, C] -> transposed split bf16 [C, R]   (R = C = DDIM)
__global__ void transpose_split(const float* __restrict__ in, bf16* __restrict__ hi,
                                bf16* __restrict__ lo) {
    __shared__ float t[32][33];
    int bx = blockIdx.x * 32, by = blockIdx.y * 32;
    int tx = threadIdx.x, ty = threadIdx.y;  // 32 x 8
    #pragma unroll
    for (int j = 0; j < 32; j += 8)
        t[ty + j][tx] = in[(size_t)(by + ty + j) * DDIM + bx + tx];
    __syncthreads();
    #pragma unroll
    for (int j = 0; j < 32; j += 8) {
        float v = t[tx][ty + j];
        size_t o = (size_t)(bx + ty + j) * DDIM + by + tx;
        bf16 h = __float2bfloat16(v);
        hi[o] = h;
        lo[o] = __float2bfloat16(v - __bfloat162float(h));
    }
}

// ---------------------------------------------------------------------------
// Split-bf16 GEMM via mma.sync:  C[M,N] = A[M,K] * B[N,K]^T,  K = 2048.
//   acc = Ah*Bh + Ah*Bl + Al*Bh in fp32 registers; the three passes are issued
//   as separate sweeps over all 16 warp tiles so no accumulator is reused
//   within ~15 HMMAs (kills RAW scoreboard stalls).
//   EPI 0: fp32 out.  EPI 1: split bf16 out.  EPI 2: split out scaled by rowscale[m].
// CTA tile 128x128x64, 8 warps (warp tile 64x32), 3-stage cp.async pipeline.
// ---------------------------------------------------------------------------
template <int EPI>
__global__ __launch_bounds__(256, 1)
void gemm_split(const bf16* __restrict__ Ah_g, const bf16* __restrict__ Al_g,
                const bf16* __restrict__ Bh_g, const bf16* __restrict__ Bl_g,
                float* __restrict__ Cf, bf16* __restrict__ Chi, bf16* __restrict__ Clo,
                const float* __restrict__ rowscale)
{
    extern __shared__ __align__(128) char smem[];
    const uint32_t sb = smem_u32(smem);

    constexpr int K = KDIM, BK = 64, NC = K / BK, S = 3;
    constexpr uint32_t TILE = 128 * 128;     // one operand tile: 128 rows x 128 bytes
    constexpr uint32_t STAGE = 4 * TILE;     // Ah, Al, Bh, Bl = 64 KB

    const int tid = threadIdx.x;
    const int m0 = blockIdx.y * 128;
    const int n0 = blockIdx.x * 128;
    const int ldc = gridDim.x * 128;
    const int wid = tid >> 5, lane = tid & 31;
    const int wm = (wid >> 2) * 64;   // warp row offset (0 / 64)
    const int wn = (wid & 3) * 32;    // warp col offset (0/32/64/96)

    // cp.async mapping: each thread does 16 x 16B per stage
    const int lrow = tid >> 3;        // 0..31
    const int lg   = tid & 7;         // 16B group within 128B row
    const bf16* gp0 = Ah_g + (size_t)m0 * K;
    const bf16* gp1 = Al_g + (size_t)m0 * K;
    const bf16* gp2 = Bh_g + (size_t)n0 * K;
    const bf16* gp3 = Bl_g + (size_t)n0 * K;

    auto load_stage = [&](int slot, int c) {
        const uint32_t base = sb + (uint32_t)slot * STAGE;
        const int k0 = c * BK + lg * 8;
        #pragma unroll
        for (int t = 0; t < 4; t++) {
            const bf16* bp = (t == 0) ? gp0 : (t == 1) ? gp1 : (t == 2) ? gp2 : gp3;
            #pragma unroll
            for (int j = 0; j < 4; j++) {
                const int row = lrow + 32 * j;
                uint32_t dst = base + (uint32_t)t * TILE + (uint32_t)row * 128
                             + (((uint32_t)lg * 16) ^ (((uint32_t)row & 7) << 4));
                cp_async16(dst, bp + (size_t)row * K + k0);
            }
        }
        cp_commit();
    };

    float acc[4][4][4];
    #pragma unroll
    for (int a = 0; a < 4; a++)
        #pragma unroll
        for (int b = 0; b < 4; b++)
            #pragma unroll
            for (int q = 0; q < 4; q++) acc[a][b][q] = 0.0f;

    load_stage(0, 0);
    load_stage(1, 1);

    // ldmatrix lane components
    const int a_row_l = lane & 15;                       // row within 16-row tile
    const int a_kb_l  = (lane >> 4) * 16;                // 0 or 16 bytes (k halves)
    const int b_n_l   = (lane & 7) + ((lane >> 4) << 3); // row within 16-col group
    const int b_kb_l  = ((lane >> 3) & 1) * 16;

    for (int c = 0; c < NC; c++) {
        if (c + 1 < NC) cp_wait<1>(); else cp_wait<0>();
        __syncthreads();
        if (c + 2 < NC) load_stage((c + 2) % S, c + 2);

        const uint32_t stg = sb + (uint32_t)(c % S) * STAGE;
        const uint32_t As_h = stg, As_l = stg + TILE;
        const uint32_t Bs_h = stg + 2 * TILE, Bs_l = stg + 3 * TILE;

        #pragma unroll
        for (int s = 0; s < 4; s++) {          // 4 k16 steps per 64-chunk
            const int kb = s * 32;             // byte offset of this k16
            uint32_t ah[4][4], al[4][4], bh[4][2], bl[4][2];
            #pragma unroll
            for (int mi = 0; mi < 4; mi++) {
                const int row = wm + mi * 16 + a_row_l;
                const uint32_t off = (uint32_t)row * 128
                    + (((uint32_t)(kb + a_kb_l)) ^ (((uint32_t)row & 7) << 4));
                LDSM_X4(ah[mi][0], ah[mi][1], ah[mi][2], ah[mi][3], As_h + off);
                LDSM_X4(al[mi][0], al[mi][1], al[mi][2], al[mi][3], As_l + off);
            }
            #pragma unroll
            for (int nj2 = 0; nj2 < 2; nj2++) {
                const int nr = wn + nj2 * 16 + b_n_l;
                const uint32_t off = (uint32_t)nr * 128
                    + (((uint32_t)(kb + b_kb_l)) ^ (((uint32_t)nr & 7) << 4));
                LDSM_X4(bh[2*nj2][0], bh[2*nj2][1], bh[2*nj2+1][0], bh[2*nj2+1][1], Bs_h + off);
                LDSM_X4(bl[2*nj2][0], bl[2*nj2][1], bl[2*nj2+1][0], bl[2*nj2+1][1], Bs_l + off);
            }
            // Three separate sweeps: 16 independent accumulators between any
            // two HMMAs that share an accumulator -> no RAW stalls.
            #pragma unroll
            for (int mi = 0; mi < 4; mi++)
                #pragma unroll
                for (int nj = 0; nj < 4; nj++)
                    mma_bf16(acc[mi][nj], ah[mi], bh[nj]);
            #pragma unroll
            for (int mi = 0; mi < 4; mi++)
                #pragma unroll
                for (int nj = 0; nj < 4; nj++)
                    mma_bf16(acc[mi][nj], ah[mi], bl[nj]);
            #pragma unroll
            for (int mi = 0; mi < 4; mi++)
                #pragma unroll
                for (int nj = 0; nj < 4; nj++)
                    mma_bf16(acc[mi][nj], al[mi], bh[nj]);
        }
    }

    // ---------------- epilogue ----------------
    const int g  = lane >> 2;
    const int t4 = lane & 3;
    #pragma unroll
    for (int mi = 0; mi < 4; mi++) {
        const int r0 = m0 + wm + mi * 16 + g;
        const int r1 = r0 + 8;
        float rs0 = 1.0f, rs1 = 1.0f;
        if (EPI == 2) { rs0 = rowscale[r0]; rs1 = rowscale[r1]; }
        #pragma unroll
        for (int nj = 0; nj < 4; nj++) {
            const int col = n0 + wn + nj * 8 + t4 * 2;
            float c0 = acc[mi][nj][0], c1 = acc[mi][nj][1];
            float c2 = acc[mi][nj][2], c3 = acc[mi][nj][3];
            if (EPI == 0) {
                float2 v0; v0.x = c0; v0.y = c1;
                float2 v1; v1.x = c2; v1.y = c3;
                *(float2*)(Cf + (size_t)r0 * ldc + col) = v0;
                *(float2*)(Cf + (size_t)r1 * ldc + col) = v1;
            } else {
                c0 *= rs0; c1 *= rs0; c2 *= rs1; c3 *= rs1;
                bf16 h0 = __float2bfloat16(c0), h1 = __float2bfloat16(c1);
                bf16 h2 = __float2bfloat16(c2), h3 = __float2bfloat16(c3);
                __nv_bfloat162 hp0; hp0.x = h0; hp0.y = h1;
                __nv_bfloat162 hp1; hp1.x = h2; hp1.y = h3;
                __nv_bfloat162 lp0, lp1;
                lp0.x = __float2bfloat16(c0 - __bfloat162float(h0));
                lp0.y = __float2bfloat16(c1 - __bfloat162float(h1));
                lp1.x = __float2bfloat16(c2 - __bfloat162float(h2));
                lp1.y = __float2bfloat16(c3 - __bfloat162float(h3));
                *(__nv_bfloat162*)(Chi + (size_t)r0 * ldc + col) = hp0;
                *(__nv_bfloat162*)(Chi + (size_t)r1 * ldc + col) = hp1;
                *(__nv_bfloat162*)(Clo + (size_t)r0 * ldc + col) = lp0;
                *(__nv_bfloat162*)(Clo + (size_t)r1 * ldc + col) = lp1;
            }
        }
    }
}

// ---------------------------------------------------------------------------
// Launch
// ---------------------------------------------------------------------------
static constexpr int GEMM_SMEM = 3 * 4 * 128 * 128;  // 196608 bytes

extern "C" void kernel_launch(void* const* d_in, const int* in_sizes, int n_in,
                              void* d_out, int out_size) {
    const float* x         = (const float*)d_in[0];  // [N, D]
    const float* lora_A    = (const float*)d_in[1];  // [r, i]
    const float* lora_B    = (const float*)d_in[2];  // [o, r]
    const float* magnitude = (const float*)d_in[3];  // [D]
    const float* direction = (const float*)d_in[4];  // [oo, i]
    float* out = (float*)d_out;                      // [N, D]

    bf16 *x_hi, *x_lo, *lB_hi, *lB_lo, *lAT_hi, *lAT_lo, *dir_hi, *dir_lo;
    bf16 *P_hi, *P_lo, *QT_hi, *QT_lo;
    float* cs;
    cudaGetSymbolAddress((void**)&x_hi, g_x_hi);   cudaGetSymbolAddress((void**)&x_lo, g_x_lo);
    cudaGetSymbolAddress((void**)&lB_hi, g_lB_hi); cudaGetSymbolAddress((void**)&lB_lo, g_lB_lo);
    cudaGetSymbolAddress((void**)&lAT_hi, g_lAT_hi); cudaGetSymbolAddress((void**)&lAT_lo, g_lAT_lo);
    cudaGetSymbolAddress((void**)&dir_hi, g_dir_hi); cudaGetSymbolAddress((void**)&dir_lo, g_dir_lo);
    cudaGetSymbolAddress((void**)&P_hi, g_P_hi);   cudaGetSymbolAddress((void**)&P_lo, g_P_lo);
    cudaGetSymbolAddress((void**)&QT_hi, g_QT_hi); cudaGetSymbolAddress((void**)&QT_lo, g_QT_lo);
    cudaGetSymbolAddress((void**)&cs, g_cs);

    cudaFuncSetAttribute(gemm_split<0>, cudaFuncAttributeMaxDynamicSharedMemorySize, GEMM_SMEM);
    cudaFuncSetAttribute(gemm_split<1>, cudaFuncAttributeMaxDynamicSharedMemorySize, GEMM_SMEM);
    cudaFuncSetAttribute(gemm_split<2>, cudaFuncAttributeMaxDynamicSharedMemorySize, GEMM_SMEM);

    // Prep: norms + split conversions
    mag_kernel<<<1, 256>>>(magnitude);
    colscale_kernel<<<DDIM, 256>>>(direction);

    const int nX8 = (NTOK * DDIM) / 8, nD8 = (DDIM * DDIM) / 8;
    split_convert<<<(nX8 + 255) / 256, 256>>>(x, x_hi, x_lo, nX8);
    split_convert<<<(nD8 + 255) / 256, 256>>>(lora_B, lB_hi, lB_lo, nD8);
    split_convert<<<(nD8 + 255) / 256, 256>>>(direction, dir_hi, dir_lo, nD8);
    dim3 tgrid(DDIM / 32, DDIM / 32), tblk(32, 8);
    transpose_split<<<tgrid, tblk>>>(lora_A, lAT_hi, lAT_lo);

    // GEMM 1: P[o,i] = sum_r lora_B[o,r] * lora_A_T[i,r]   (split epilogue)
    dim3 gs(DDIM / 128, DDIM / 128);
    gemm_split<1><<<gs, 256, GEMM_SMEM>>>(lB_hi, lB_lo, lAT_hi, lAT_lo,
                                          nullptr, P_hi, P_lo, nullptr);
    // GEMM 2: QT[oo,o] = cs[oo] * sum_i direction[oo,i] * P[o,i]  (split + rowscale)
    gemm_split<2><<<gs, 256, GEMM_SMEM>>>(dir_hi, dir_lo, P_hi, P_lo,
                                          nullptr, QT_hi, QT_lo, cs);
    // GEMM 3: out[n,oo] = sum_o x[n,o] * QT[oo,o]   (fp32 epilogue)
    dim3 gb(DDIM / 128, NTOK / 128);
    gemm_split<0><<<gb, 256, GEMM_SMEM>>>(x_hi, x_lo, QT_hi, QT_lo,
                                          out, nullptr, nullptr, nullptr);
}

// round 5
// speedup vs baseline: 5.7338x; 1.0166x over previous
#include <cuda_runtime.h>
#include <cuda_bf16.h>
#include <cstdint>
#include <math.h>

typedef __nv_bfloat16 bf16;

#define NTOK 8192
#define DDIM 2048
#define KDIM 2048
#define SCALING_F (16.0f / 2048.0f)
#define EPS_F 1e-12f

// ---------------------------------------------------------------------------
// Static device scratch (allocation-free per harness rules)
// ---------------------------------------------------------------------------
__device__ bf16 g_x_hi [(size_t)NTOK * DDIM];
__device__ bf16 g_x_lo [(size_t)NTOK * DDIM];
__device__ bf16 g_lB_hi[(size_t)DDIM * DDIM];
__device__ bf16 g_lB_lo[(size_t)DDIM * DDIM];
__device__ bf16 g_lAT_hi[(size_t)DDIM * DDIM];   // lora_A transposed [i, r]
__device__ bf16 g_lAT_lo[(size_t)DDIM * DDIM];
__device__ bf16 g_dir_hi[(size_t)DDIM * DDIM];
__device__ bf16 g_dir_lo[(size_t)DDIM * DDIM];
__device__ bf16 g_P_hi [(size_t)DDIM * DDIM];    // P = lora_B @ lora_A  [o, i]
__device__ bf16 g_P_lo [(size_t)DDIM * DDIM];
__device__ bf16 g_QT_hi[(size_t)DDIM * DDIM];    // QT[oo,o] = cs[oo]*(dir @ P^T)
__device__ bf16 g_QT_lo[(size_t)DDIM * DDIM];
__device__ float g_cs[DDIM];

// ---------------------------------------------------------------------------
// PTX helpers — standard features only (sm_80+): cp.async, ldmatrix, mma.sync
// ---------------------------------------------------------------------------
__device__ __forceinline__ uint32_t smem_u32(const void* p) {
    uint32_t a;
    asm("{ .reg .u64 t; cvta.to.shared.u64 t, %1; cvt.u32.u64 %0, t; }" : "=r"(a) : "l"(p));
    return a;
}

__device__ __forceinline__ void cp_async16(uint32_t dst, const void* src) {
    asm volatile("cp.async.cg.shared.global [%0], [%1], 16;" :: "r"(dst), "l"(src));
}
__device__ __forceinline__ void cp_commit() { asm volatile("cp.async.commit_group;" ::: "memory"); }
template <int N>
__device__ __forceinline__ void cp_wait() { asm volatile("cp.async.wait_group %0;" :: "n"(N) : "memory"); }

#define LDSM_X4(r0, r1, r2, r3, addr) \
    asm volatile("ldmatrix.sync.aligned.m8n8.x4.shared.b16 {%0,%1,%2,%3}, [%4];" \
        : "=r"(r0), "=r"(r1), "=r"(r2), "=r"(r3) : "r"(addr))

__device__ __forceinline__ void mma_bf16(float* c, const uint32_t* a, const uint32_t* b) {
    asm volatile(
        "mma.sync.aligned.m16n8k16.row.col.f32.bf16.bf16.f32 "
        "{%0,%1,%2,%3}, {%4,%5,%6,%7}, {%8,%9}, {%0,%1,%2,%3};"
        : "+f"(c[0]), "+f"(c[1]), "+f"(c[2]), "+f"(c[3])
        : "r"(a[0]), "r"(a[1]), "r"(a[2]), "r"(a[3]), "r"(b[0]), "r"(b[1]));
}

// ---------------------------------------------------------------------------
// Prep kernel 1: fused mag + colscale.
//   Each block o: cs[o] = ||magnitude|| * SCALING / max(||direction[o,:]||, eps)
//   (mag recomputed per block — 2048 extra loads, trivial.)
// ---------------------------------------------------------------------------
__global__ void magcol_kernel(const float* __restrict__ magnitude,
                              const float* __restrict__ direction) {
    int o = blockIdx.x;
    const float* row = direction + (size_t)o * DDIM;
    float sm = 0.0f, sd = 0.0f;
    for (int i = threadIdx.x; i < DDIM; i += 256) {
        float a = magnitude[i];  sm += a * a;
        float b = row[i];        sd += b * b;
    }
    __shared__ float rm[256], rd[256];
    rm[threadIdx.x] = sm; rd[threadIdx.x] = sd;
    __syncthreads();
    for (int off = 128; off > 0; off >>= 1) {
        if (threadIdx.x < off) {
            rm[threadIdx.x] += rm[threadIdx.x + off];
            rd[threadIdx.x] += rd[threadIdx.x + off];
        }
        __syncthreads();
    }
    if (threadIdx.x == 0)
        g_cs[o] = sqrtf(rm[0]) * SCALING_F / fmaxf(sqrtf(rd[0]), EPS_F);
}

// ---------------------------------------------------------------------------
// Prep kernel 2: fused split of x, lora_B, direction (8 floats/thread).
// ---------------------------------------------------------------------------
__device__ __forceinline__ void split8(const float* __restrict__ in,
                                       bf16* __restrict__ hi, bf16* __restrict__ lo,
                                       int i) {
    float4 a = ((const float4*)in)[i * 2];
    float4 b = ((const float4*)in)[i * 2 + 1];
    float v[8] = {a.x, a.y, a.z, a.w, b.x, b.y, b.z, b.w};
    uint32_t hw[4], lw[4];
    #pragma unroll
    for (int q = 0; q < 4; q++) {
        bf16 h0 = __float2bfloat16(v[q * 2]);
        bf16 h1 = __float2bfloat16(v[q * 2 + 1]);
        __nv_bfloat162 hp; hp.x = h0; hp.y = h1;
        hw[q] = *(uint32_t*)&hp;
        __nv_bfloat162 lp;
        lp.x = __float2bfloat16(v[q * 2] - __bfloat162float(h0));
        lp.y = __float2bfloat16(v[q * 2 + 1] - __bfloat162float(h1));
        lw[q] = *(uint32_t*)&lp;
    }
    uint4 hv; hv.x = hw[0]; hv.y = hw[1]; hv.z = hw[2]; hv.w = hw[3];
    uint4 lv; lv.x = lw[0]; lv.y = lw[1]; lv.z = lw[2]; lv.w = lw[3];
    ((uint4*)hi)[i] = hv;
    ((uint4*)lo)[i] = lv;
}

#define NX8 ((NTOK * DDIM) / 8)     // 2097152
#define ND8 ((DDIM * DDIM) / 8)     // 524288
#define BX  (NX8 / 256)             // 8192 blocks for x
#define BD  (ND8 / 256)             // 2048 blocks per weight

__global__ void fused_split(const float* __restrict__ x,
                            const float* __restrict__ lB,
                            const float* __restrict__ dir,
                            bf16* __restrict__ xh, bf16* __restrict__ xl,
                            bf16* __restrict__ lBh, bf16* __restrict__ lBl,
                            bf16* __restrict__ dh,  bf16* __restrict__ dl) {
    int b = blockIdx.x;
    if (b < BX) {
        split8(x, xh, xl, b * 256 + threadIdx.x);
    } else if (b < BX + BD) {
        split8(lB, lBh, lBl, (b - BX) * 256 + threadIdx.x);
    } else {
        split8(dir, dh, dl, (b - BX - BD) * 256 + threadIdx.x);
    }
}

// fp32 [R, C] -> transposed split bf16 [C, R]   (R = C = DDIM)
__global__ void transpose_split(const float* __restrict__ in, bf16* __restrict__ hi,
                                bf16* __restrict__ lo) {
    __shared__ float t[32][33];
    int bx = blockIdx.x * 32, by = blockIdx.y * 32;
    int tx = threadIdx.x, ty = threadIdx.y;  // 32 x 8
    #pragma unroll
    for (int j = 0; j < 32; j += 8)
        t[ty + j][tx] = in[(size_t)(by + ty + j) * DDIM + bx + tx];
    __syncthreads();
    #pragma unroll
    for (int j = 0; j < 32; j += 8) {
        float v = t[tx][ty + j];
        size_t o = (size_t)(bx + ty + j) * DDIM + by + tx;
        bf16 h = __float2bfloat16(v);
        hi[o] = h;
        lo[o] = __float2bfloat16(v - __bfloat162float(h));
    }
}

// ---------------------------------------------------------------------------
// Split-bf16 GEMM via mma.sync:  C[M,N] = A[M,K] * B[N,K]^T,  K = 2048.
//   acc = Ah*Bh + Ah*Bl + Al*Bh (fp32 regs). Fragments for k16 step s+1 are
//   prefetched via ldmatrix while step s computes (double-buffered frags).
//   EPI 0: fp32 out.  EPI 1: split bf16 out.  EPI 2: split out * rowscale[m].
// CTA tile 128x128x64, 8 warps (warp tile 64x32), 3-stage cp.async pipeline.
// ---------------------------------------------------------------------------
template <int EPI>
__global__ __launch_bounds__(256, 1)
void gemm_split(const bf16* __restrict__ Ah_g, const bf16* __restrict__ Al_g,
                const bf16* __restrict__ Bh_g, const bf16* __restrict__ Bl_g,
                float* __restrict__ Cf, bf16* __restrict__ Chi, bf16* __restrict__ Clo,
                const float* __restrict__ rowscale)
{
    extern __shared__ __align__(128) char smem[];
    const uint32_t sb = smem_u32(smem);

    constexpr int K = KDIM, BK = 64, NC = K / BK, S = 3;
    constexpr uint32_t TILE = 128 * 128;     // one operand tile: 128 rows x 128 bytes
    constexpr uint32_t STAGE = 4 * TILE;     // Ah, Al, Bh, Bl = 64 KB

    const int tid = threadIdx.x;
    const int m0 = blockIdx.y * 128;
    const int n0 = blockIdx.x * 128;
    const int ldc = gridDim.x * 128;
    const int wid = tid >> 5, lane = tid & 31;
    const int wm = (wid >> 2) * 64;   // warp row offset (0 / 64)
    const int wn = (wid & 3) * 32;    // warp col offset (0/32/64/96)

    // cp.async mapping: each thread does 16 x 16B per stage
    const int lrow = tid >> 3;        // 0..31
    const int lg   = tid & 7;         // 16B group within 128B row
    const bf16* gp0 = Ah_g + (size_t)m0 * K;
    const bf16* gp1 = Al_g + (size_t)m0 * K;
    const bf16* gp2 = Bh_g + (size_t)n0 * K;
    const bf16* gp3 = Bl_g + (size_t)n0 * K;

    auto load_stage = [&](int slot, int c) {
        const uint32_t base = sb + (uint32_t)slot * STAGE;
        const int k0 = c * BK + lg * 8;
        #pragma unroll
        for (int t = 0; t < 4; t++) {
            const bf16* bp = (t == 0) ? gp0 : (t == 1) ? gp1 : (t == 2) ? gp2 : gp3;
            #pragma unroll
            for (int j = 0; j < 4; j++) {
                const int row = lrow + 32 * j;
                uint32_t dst = base + (uint32_t)t * TILE + (uint32_t)row * 128
                             + (((uint32_t)lg * 16) ^ (((uint32_t)row & 7) << 4));
                cp_async16(dst, bp + (size_t)row * K + k0);
            }
        }
        cp_commit();
    };

    float acc[4][4][4];
    #pragma unroll
    for (int a = 0; a < 4; a++)
        #pragma unroll
        for (int b = 0; b < 4; b++)
            #pragma unroll
            for (int q = 0; q < 4; q++) acc[a][b][q] = 0.0f;

    load_stage(0, 0);
    load_stage(1, 1);

    // ldmatrix lane components
    const int a_row_l = lane & 15;                       // row within 16-row tile
    const int a_kb_l  = (lane >> 4) * 16;                // 0 or 16 bytes (k halves)
    const int b_n_l   = (lane & 7) + ((lane >> 4) << 3); // row within 16-col group
    const int b_kb_l  = ((lane >> 3) & 1) * 16;

    // double-buffered fragments
    uint32_t ah[2][4][4], al[2][4][4], bh[2][4][2], bl[2][4][2];

    for (int c = 0; c < NC; c++) {
        if (c + 1 < NC) cp_wait<1>(); else cp_wait<0>();
        __syncthreads();
        if (c + 2 < NC) load_stage((c + 2) % S, c + 2);

        const uint32_t stg = sb + (uint32_t)(c % S) * STAGE;
        const uint32_t As_h = stg, As_l = stg + TILE;
        const uint32_t Bs_h = stg + 2 * TILE, Bs_l = stg + 3 * TILE;

        auto load_frags = [&](int buf, int s) {
            const int kb = s * 32;
            #pragma unroll
            for (int mi = 0; mi < 4; mi++) {
                const int row = wm + mi * 16 + a_row_l;
                const uint32_t off = (uint32_t)row * 128
                    + (((uint32_t)(kb + a_kb_l)) ^ (((uint32_t)row & 7) << 4));
                LDSM_X4(ah[buf][mi][0], ah[buf][mi][1], ah[buf][mi][2], ah[buf][mi][3], As_h + off);
                LDSM_X4(al[buf][mi][0], al[buf][mi][1], al[buf][mi][2], al[buf][mi][3], As_l + off);
            }
            #pragma unroll
            for (int nj2 = 0; nj2 < 2; nj2++) {
                const int nr = wn + nj2 * 16 + b_n_l;
                const uint32_t off = (uint32_t)nr * 128
                    + (((uint32_t)(kb + b_kb_l)) ^ (((uint32_t)nr & 7) << 4));
                LDSM_X4(bh[buf][2*nj2][0], bh[buf][2*nj2][1],
                        bh[buf][2*nj2+1][0], bh[buf][2*nj2+1][1], Bs_h + off);
                LDSM_X4(bl[buf][2*nj2][0], bl[buf][2*nj2][1],
                        bl[buf][2*nj2+1][0], bl[buf][2*nj2+1][1], Bs_l + off);
            }
        };

        load_frags(0, 0);
        #pragma unroll
        for (int s = 0; s < 4; s++) {
            const int cur = s & 1;
            if (s < 3) load_frags(cur ^ 1, s + 1);
            // Three sweeps over 16 independent accumulators each.
            #pragma unroll
            for (int mi = 0; mi < 4; mi++)
                #pragma unroll
                for (int nj = 0; nj < 4; nj++)
                    mma_bf16(acc[mi][nj], ah[cur][mi], bh[cur][nj]);
            #pragma unroll
            for (int mi = 0; mi < 4; mi++)
                #pragma unroll
                for (int nj = 0; nj < 4; nj++)
                    mma_bf16(acc[mi][nj], ah[cur][mi], bl[cur][nj]);
            #pragma unroll
            for (int mi = 0; mi < 4; mi++)
                #pragma unroll
                for (int nj = 0; nj < 4; nj++)
                    mma_bf16(acc[mi][nj], al[cur][mi], bh[cur][nj]);
        }
    }

    // ---------------- epilogue ----------------
    const int g  = lane >> 2;
    const int t4 = lane & 3;
    #pragma unroll
    for (int mi = 0; mi < 4; mi++) {
        const int r0 = m0 + wm + mi * 16 + g;
        const int r1 = r0 + 8;
        float rs0 = 1.0f, rs1 = 1.0f;
        if (EPI == 2) { rs0 = rowscale[r0]; rs1 = rowscale[r1]; }
        #pragma unroll
        for (int nj = 0; nj < 4; nj++) {
            const int col = n0 + wn + nj * 8 + t4 * 2;
            float c0 = acc[mi][nj][0], c1 = acc[mi][nj][1];
            float c2 = acc[mi][nj][2], c3 = acc[mi][nj][3];
            if (EPI == 0) {
                float2 v0; v0.x = c0; v0.y = c1;
                float2 v1; v1.x = c2; v1.y = c3;
                *(float2*)(Cf + (size_t)r0 * ldc + col) = v0;
                *(float2*)(Cf + (size_t)r1 * ldc + col) = v1;
            } else {
                c0 *= rs0; c1 *= rs0; c2 *= rs1; c3 *= rs1;
                bf16 h0 = __float2bfloat16(c0), h1 = __float2bfloat16(c1);
                bf16 h2 = __float2bfloat16(c2), h3 = __float2bfloat16(c3);
                __nv_bfloat162 hp0; hp0.x = h0; hp0.y = h1;
                __nv_bfloat162 hp1; hp1.x = h2; hp1.y = h3;
                __nv_bfloat162 lp0, lp1;
                lp0.x = __float2bfloat16(c0 - __bfloat162float(h0));
                lp0.y = __float2bfloat16(c1 - __bfloat162float(h1));
                lp1.x = __float2bfloat16(c2 - __bfloat162float(h2));
                lp1.y = __float2bfloat16(c3 - __bfloat162float(h3));
                *(__nv_bfloat162*)(Chi + (size_t)r0 * ldc + col) = hp0;
                *(__nv_bfloat162*)(Chi + (size_t)r1 * ldc + col) = hp1;
                *(__nv_bfloat162*)(Clo + (size_t)r0 * ldc + col) = lp0;
                *(__nv_bfloat162*)(Clo + (size_t)r1 * ldc + col) = lp1;
            }
        }
    }
}

// ---------------------------------------------------------------------------
// Launch: fused_split(1) -> transpose(2) -> magcol(3) -> gemm1(4) -> gemm2(5)
//         -> gemm3(6)   [ncu -s 5 -c 1 lands on gemm3]
// ---------------------------------------------------------------------------
static constexpr int GEMM_SMEM = 3 * 4 * 128 * 128;  // 196608 bytes

extern "C" void kernel_launch(void* const* d_in, const int* in_sizes, int n_in,
                              void* d_out, int out_size) {
    const float* x         = (const float*)d_in[0];  // [N, D]
    const float* lora_A    = (const float*)d_in[1];  // [r, i]
    const float* lora_B    = (const float*)d_in[2];  // [o, r]
    const float* magnitude = (const float*)d_in[3];  // [D]
    const float* direction = (const float*)d_in[4];  // [oo, i]
    float* out = (float*)d_out;                      // [N, D]

    bf16 *x_hi, *x_lo, *lB_hi, *lB_lo, *lAT_hi, *lAT_lo, *dir_hi, *dir_lo;
    bf16 *P_hi, *P_lo, *QT_hi, *QT_lo;
    float* cs;
    cudaGetSymbolAddress((void**)&x_hi, g_x_hi);   cudaGetSymbolAddress((void**)&x_lo, g_x_lo);
    cudaGetSymbolAddress((void**)&lB_hi, g_lB_hi); cudaGetSymbolAddress((void**)&lB_lo, g_lB_lo);
    cudaGetSymbolAddress((void**)&lAT_hi, g_lAT_hi); cudaGetSymbolAddress((void**)&lAT_lo, g_lAT_lo);
    cudaGetSymbolAddress((void**)&dir_hi, g_dir_hi); cudaGetSymbolAddress((void**)&dir_lo, g_dir_lo);
    cudaGetSymbolAddress((void**)&P_hi, g_P_hi);   cudaGetSymbolAddress((void**)&P_lo, g_P_lo);
    cudaGetSymbolAddress((void**)&QT_hi, g_QT_hi); cudaGetSymbolAddress((void**)&QT_lo, g_QT_lo);
    cudaGetSymbolAddress((void**)&cs, g_cs);

    cudaFuncSetAttribute(gemm_split<0>, cudaFuncAttributeMaxDynamicSharedMemorySize, GEMM_SMEM);
    cudaFuncSetAttribute(gemm_split<1>, cudaFuncAttributeMaxDynamicSharedMemorySize, GEMM_SMEM);
    cudaFuncSetAttribute(gemm_split<2>, cudaFuncAttributeMaxDynamicSharedMemorySize, GEMM_SMEM);

    // 1: fused split of x, lora_B, direction
    fused_split<<<BX + 2 * BD, 256>>>(x, lora_B, direction,
                                      x_hi, x_lo, lB_hi, lB_lo, dir_hi, dir_lo);
    // 2: transpose+split lora_A
    dim3 tgrid(DDIM / 32, DDIM / 32), tblk(32, 8);
    transpose_split<<<tgrid, tblk>>>(lora_A, lAT_hi, lAT_lo);
    // 3: fused mag + colscale
    magcol_kernel<<<DDIM, 256>>>(magnitude, direction);

    // 4: P[o,i] = sum_r lora_B[o,r] * lora_A_T[i,r]   (split epilogue)
    dim3 gs(DDIM / 128, DDIM / 128);
    gemm_split<1><<<gs, 256, GEMM_SMEM>>>(lB_hi, lB_lo, lAT_hi, lAT_lo,
                                          nullptr, P_hi, P_lo, nullptr);
    // 5: QT[oo,o] = cs[oo] * sum_i direction[oo,i] * P[o,i]  (split + rowscale)
    gemm_split<2><<<gs, 256, GEMM_SMEM>>>(dir_hi, dir_lo, P_hi, P_lo,
                                          nullptr, QT_hi, QT_lo, cs);
    // 6: out[n,oo] = sum_o x[n,o] * QT[oo,o]   (fp32 epilogue)
    dim3 gb(DDIM / 128, NTOK / 128);
    gemm_split<0><<<gb, 256, GEMM_SMEM>>>(x_hi, x_lo, QT_hi, QT_lo,
                                          out, nullptr, nullptr, nullptr);
}